// round 3
// baseline (speedup 1.0000x reference)
#include <cuda_runtime.h>
#include <math.h>

#define OC 32
#define MAXN 100000
#define MAXE 1600000

// ---- scratch (device globals; referenced ONLY from device code) ----
__device__ float g_y_tp  [MAXN * OC];
__device__ float g_y_int [MAXN * OC];
__device__ float g_y_tp2 [MAXN * OC];
__device__ float g_y_int2[MAXN * OC];
__device__ float g_h     [MAXN * OC];
__device__ float g_inv   [MAXN];
__device__ int   g_cnt_tp [MAXN];
__device__ int   g_cnt_int[MAXN];
__device__ int   g_off_tp [MAXN + 1];
__device__ int   g_off_int[MAXN + 1];
__device__ int   g_cur_tp [MAXN];
__device__ int   g_cur_int[MAXN];
__device__ int   g_csr_tp [MAXE];
__device__ int   g_csr_int[MAXE];

// ------------------------------------------------------------------
__global__ void k_zero_cnt(int n) {
    int i = blockIdx.x * blockDim.x + threadIdx.x;
    if (i < n) { g_cnt_tp[i] = 0; g_cnt_int[i] = 0; }
}

// degree count for both edge types in one launch
__global__ void k_count(const int* __restrict__ tp_dst,
                        const int* __restrict__ int_dst, int E) {
    int t = blockIdx.x * blockDim.x + threadIdx.x;
    if (t < E)              atomicAdd(&g_cnt_tp[tp_dst[t]], 1);
    else if (t < 2 * E)     atomicAdd(&g_cnt_int[int_dst[t - E]], 1);
}

// ------------------------------------------------------------------
// single-block exclusive scan building off / cur (and inv for 'int')
__device__ void scan_build(const int* __restrict__ cnt,
                           int* __restrict__ off,
                           int* __restrict__ cur,
                           float* __restrict__ inv,
                           int n, int* sh) {
    int tid = threadIdx.x;
    int chunk = (n + 1023) >> 10;
    int lo = tid * chunk;
    int hi = min(lo + chunk, n);
    int s = 0;
    for (int i = lo; i < hi; i++) s += cnt[i];
    sh[tid] = s;
    __syncthreads();
    for (int d = 1; d < 1024; d <<= 1) {          // inclusive scan
        int t = (tid >= d) ? sh[tid - d] : 0;
        __syncthreads();
        sh[tid] += t;
        __syncthreads();
    }
    int run = sh[tid] - s;                         // exclusive prefix
    for (int i = lo; i < hi; i++) {
        off[i] = run;
        cur[i] = run;
        if (inv) inv[i] = 1.f / fmaxf((float)cnt[i], 1.f);
        run += cnt[i];
    }
    if (tid == 1023) off[n] = run;                 // total (sh[1023] inclusive)
    __syncthreads();
}

__global__ void k_scan(int n) {
    __shared__ int sh[1024];
    scan_build(g_cnt_tp,  g_off_tp,  g_cur_tp,  0,     n, sh);
    scan_build(g_cnt_int, g_off_int, g_cur_int, g_inv, n, sh);
}

// ------------------------------------------------------------------
// fill CSR adjacency (src ids grouped by dst) for both edge types
__global__ void k_fill(const int* __restrict__ tp_src,
                       const int* __restrict__ tp_dst,
                       const int* __restrict__ int_src,
                       const int* __restrict__ int_dst, int E) {
    int t = blockIdx.x * blockDim.x + threadIdx.x;
    if (t < E) {
        int pos = atomicAdd(&g_cur_tp[tp_dst[t]], 1);
        g_csr_tp[pos] = tp_src[t];
    } else if (t < 2 * E) {
        int e = t - E;
        int pos = atomicAdd(&g_cur_int[int_dst[e]], 1);
        g_csr_int[pos] = int_src[e];
    }
}

// ------------------------------------------------------------------
// block-1 transforms: y = x @ W  (Cin=6). warp/node, lane=channel
__global__ void k_transform6(const float* __restrict__ x,
                             const float* __restrict__ Wtp,
                             const float* __restrict__ Wint,
                             int n_node) {
    int t = blockIdx.x * blockDim.x + threadIdx.x;
    int node = t >> 5;
    int c = t & 31;
    if (node >= n_node) return;
    float a = 0.f, b = 0.f;
#pragma unroll
    for (int k = 0; k < 6; k++) {
        float xv = __ldg(&x[node * 6 + k]);
        a = fmaf(xv, __ldg(&Wtp[k * OC + c]), a);
        b = fmaf(xv, __ldg(&Wint[k * OC + c]), b);
    }
    g_y_tp[node * OC + c]  = a;
    g_y_int[node * OC + c] = b;
}

// ------------------------------------------------------------------
// gather-sum over a CSR neighbor list: sum_j y[csr[j]*32 + c]
__device__ __forceinline__ float gather_sum(const int* __restrict__ csr,
                                            int beg, int end,
                                            const float* __restrict__ y,
                                            int c) {
    float acc = 0.f;
    for (int i = beg; i < end; i += 32) {
        int m = min(32, end - i);
        int sv = (c < m) ? __ldg(&csr[i + c]) : 0;
        int j = 0;
        for (; j + 4 <= m; j += 4) {
            int s0 = __shfl_sync(0xffffffffu, sv, j);
            int s1 = __shfl_sync(0xffffffffu, sv, j + 1);
            int s2 = __shfl_sync(0xffffffffu, sv, j + 2);
            int s3 = __shfl_sync(0xffffffffu, sv, j + 3);
            float v0 = __ldg(&y[s0 * OC + c]);
            float v1 = __ldg(&y[s1 * OC + c]);
            float v2 = __ldg(&y[s2 * OC + c]);
            float v3 = __ldg(&y[s3 * OC + c]);
            acc += (v0 + v1) + (v2 + v3);
        }
        for (; j < m; j++) {
            int sj = __shfl_sync(0xffffffffu, sv, j);
            acc += __ldg(&y[sj * OC + c]);
        }
    }
    return acc;
}

// ------------------------------------------------------------------
// combine block 1: gathers + relu(x@(Ws+Wres)+b+m_tp+m_int),
// fused with block-2 transforms (writes y2 arrays). warp/node, lane=ch.
__global__ void k_combine1(const float* __restrict__ x,
                           const float* __restrict__ Ws,
                           const float* __restrict__ b,
                           const float* __restrict__ Wres,
                           const float* __restrict__ Wtp2,
                           const float* __restrict__ Wint2,
                           int n_node) {
    __shared__ float sWtp[OC * OC];
    __shared__ float sWint[OC * OC];
    for (int i = threadIdx.x; i < OC * OC; i += blockDim.x) {
        sWtp[i]  = Wtp2[i];
        sWint[i] = Wint2[i];
    }
    __syncthreads();

    int t = blockIdx.x * blockDim.x + threadIdx.x;
    int node = t >> 5;
    int c = t & 31;
    if (node >= n_node) return;

    float m_tp  = gather_sum(g_csr_tp,  g_off_tp[node],  g_off_tp[node + 1],  g_y_tp,  c);
    float m_int = gather_sum(g_csr_int, g_off_int[node], g_off_int[node + 1], g_y_int, c)
                  * g_inv[node];

    float acc = __ldg(&b[c]);
#pragma unroll
    for (int k = 0; k < 6; k++) {
        float xv = __ldg(&x[node * 6 + k]);
        acc = fmaf(xv, __ldg(&Ws[k * OC + c]) + __ldg(&Wres[k * OC + c]), acc);
    }
    acc += m_tp + m_int;
    float h = fmaxf(acc, 0.f);
    int o = node * OC + c;
    g_h[o] = h;

    // block-2 transforms on fresh h (broadcast across warp)
    float atp = 0.f, ain = 0.f;
#pragma unroll
    for (int k = 0; k < OC; k++) {
        float hk = __shfl_sync(0xffffffffu, h, k);
        atp = fmaf(hk, sWtp[k * OC + c], atp);
        ain = fmaf(hk, sWint[k * OC + c], ain);
    }
    g_y_tp2[o]  = atp;
    g_y_int2[o] = ain;
}

// ------------------------------------------------------------------
// combine block 2 (identity residual) + decoder MLP + sigmoid.
__global__ void k_combine2(const float* __restrict__ Ws2,
                           const float* __restrict__ b2,
                           const float* __restrict__ Wd1,
                           const float* __restrict__ bd1,
                           const float* __restrict__ Wd2,
                           const float* __restrict__ bd2,
                           float* __restrict__ out,
                           int n_node) {
    __shared__ float sWs[OC * OC];
    __shared__ float sWd1[OC * OC];
    for (int i = threadIdx.x; i < OC * OC; i += blockDim.x) {
        sWs[i]  = Ws2[i];
        sWd1[i] = Wd1[i];
    }
    __syncthreads();

    int t = blockIdx.x * blockDim.x + threadIdx.x;
    int node = t >> 5;
    int c = t & 31;
    if (node >= n_node) return;

    float m_tp  = gather_sum(g_csr_tp,  g_off_tp[node],  g_off_tp[node + 1],  g_y_tp2,  c);
    float m_int = gather_sum(g_csr_int, g_off_int[node], g_off_int[node + 1], g_y_int2, c)
                  * g_inv[node];

    int o = node * OC + c;
    float h = g_h[o];
    float acc = __ldg(&b2[c]) + h;       // identity residual
#pragma unroll
    for (int k = 0; k < OC; k++) {
        float hk = __shfl_sync(0xffffffffu, h, k);
        acc = fmaf(hk, sWs[k * OC + c], acc);
    }
    acc += m_tp + m_int;
    float h2 = fmaxf(acc, 0.f);

    // decoder layer 1
    float d = __ldg(&bd1[c]);
#pragma unroll
    for (int k = 0; k < OC; k++) {
        float hk = __shfl_sync(0xffffffffu, h2, k);
        d = fmaf(hk, sWd1[k * OC + c], d);
    }
    d = fmaxf(d, 0.f) * __ldg(&Wd2[c]);

    // decoder layer 2: warp-reduce dot product
#pragma unroll
    for (int off = 16; off > 0; off >>= 1)
        d += __shfl_xor_sync(0xffffffffu, d, off);

    if (c == 0)
        out[node] = 1.f / (1.f + __expf(-(d + __ldg(&bd2[0]))));
}

// ------------------------------------------------------------------
extern "C" void kernel_launch(void* const* d_in, const int* in_sizes, int n_in,
                              void* d_out, int out_size) {
    const float* x        = (const float*)d_in[0];
    const int*   edge_tp  = (const int*)d_in[1];
    const int*   edge_int = (const int*)d_in[2];
    const float* W_self1  = (const float*)d_in[3];
    const float* b1       = (const float*)d_in[4];
    const float* W_tp1    = (const float*)d_in[5];
    const float* W_int1   = (const float*)d_in[6];
    const float* W_res1   = (const float*)d_in[7];
    const float* W_self2  = (const float*)d_in[8];
    const float* b2       = (const float*)d_in[9];
    const float* W_tp2    = (const float*)d_in[10];
    const float* W_int2   = (const float*)d_in[11];
    const float* Wd1      = (const float*)d_in[12];
    const float* bd1      = (const float*)d_in[13];
    const float* Wd2      = (const float*)d_in[14];
    const float* bd2      = (const float*)d_in[15];
    float* out = (float*)d_out;

    const int N = in_sizes[0] / 6;        // 100000
    const int E = in_sizes[1] / 2;        // 1600000

    const int* tp_src  = edge_tp;
    const int* tp_dst  = edge_tp + E;
    const int* int_src = edge_int;
    const int* int_dst = edge_int + E;

    const int TB = 256;
    const int gNode  = (N * OC + TB - 1) / TB;   // warp-per-node kernels
    const int gN     = (N + TB - 1) / TB;
    const int gE2    = (2 * E + TB - 1) / TB;

    // CSR build (shared by both blocks)
    k_zero_cnt<<<gN, TB>>>(N);
    k_count<<<gE2, TB>>>(tp_dst, int_dst, E);
    k_scan<<<1, 1024>>>(N);
    k_fill<<<gE2, TB>>>(tp_src, tp_dst, int_src, int_dst, E);

    // block 1
    k_transform6<<<gNode, TB>>>(x, W_tp1, W_int1, N);
    k_combine1<<<gNode, TB>>>(x, W_self1, b1, W_res1, W_tp2, W_int2, N);

    // block 2 + decoder
    k_combine2<<<gNode, TB>>>(W_self2, b2, Wd1, bd1, Wd2, bd2, out, N);
}

// round 4
// speedup vs baseline: 2.4147x; 2.4147x over previous
#include <cuda_runtime.h>
#include <math.h>

#define OC 32
#define MAXN 100000
#define MAXE 1600000
#define TILE 2048
#define MAXB ((MAXN + TILE - 1) / TILE + 1)

// ---- scratch (device globals; referenced ONLY from device code) ----
__device__ float g_y_tp  [MAXN * OC];
__device__ float g_y_int [MAXN * OC];
__device__ float g_y_tp2 [MAXN * OC];
__device__ float g_y_int2[MAXN * OC];
__device__ float g_h     [MAXN * OC];
__device__ float g_inv   [MAXN];
__device__ int   g_cnt_tp [MAXN];
__device__ int   g_cnt_int[MAXN];
__device__ int   g_off_tp [MAXN + 1];
__device__ int   g_off_int[MAXN + 1];
__device__ int   g_cur_tp [MAXN];
__device__ int   g_cur_int[MAXN];
__device__ int   g_csr_tp [MAXE];
__device__ int   g_csr_int[MAXE];
__device__ int   g_bsum_tp [MAXB];
__device__ int   g_bsum_int[MAXB];

// ------------------------------------------------------------------
__global__ void k_zero_cnt(int n) {
    int i = blockIdx.x * blockDim.x + threadIdx.x;
    if (i < n) { g_cnt_tp[i] = 0; g_cnt_int[i] = 0; }
}

__global__ void k_count(const int* __restrict__ tp_dst,
                        const int* __restrict__ int_dst, int E) {
    int t = blockIdx.x * blockDim.x + threadIdx.x;
    if (t < E)          atomicAdd(&g_cnt_tp[tp_dst[t]], 1);
    else if (t < 2 * E) atomicAdd(&g_cnt_int[int_dst[t - E]], 1);
}

// ------------------------------------------------------------------
// tiled scan, step 1: per-tile exclusive prefix (coalesced) + tile sums.
// grid = 2*nb: blocks [0,nb) handle tp, [nb,2nb) handle int (also inv).
__global__ void k_scan_local(int n, int nb) {
    __shared__ int s[TILE];
    __shared__ int wtot[9];

    bool is_int = (blockIdx.x >= nb);
    int b = is_int ? blockIdx.x - nb : blockIdx.x;
    const int* __restrict__ cnt = is_int ? g_cnt_int : g_cnt_tp;
    int* __restrict__ off  = is_int ? g_off_int  : g_off_tp;
    int* __restrict__ bsum = is_int ? g_bsum_int : g_bsum_tp;

    int tid = threadIdx.x;
    int base = b * TILE;

    // coalesced load (OOB -> 0); int branch also writes inv
#pragma unroll
    for (int k = 0; k < 8; k++) {
        int idx = base + k * 256 + tid;
        int v = (idx < n) ? cnt[idx] : 0;
        s[k * 256 + tid] = v;
        if (is_int && idx < n) g_inv[idx] = 1.f / fmaxf((float)v, 1.f);
    }
    __syncthreads();

    // thread-local exclusive prefix over its 8 blocked values
    int loc[8];
    int tsum = 0;
#pragma unroll
    for (int j = 0; j < 8; j++) {
        int v = s[tid * 8 + j];
        loc[j] = tsum;
        tsum += v;
    }

    // warp inclusive scan of tsum
    int lane = tid & 31, w = tid >> 5;
    int incl = tsum;
#pragma unroll
    for (int d = 1; d < 32; d <<= 1) {
        int t = __shfl_up_sync(0xffffffffu, incl, d);
        if (lane >= d) incl += t;
    }
    int wexcl = incl - tsum;
    if (lane == 31) wtot[w] = incl;
    __syncthreads();
    if (tid == 0) {
        int r = 0;
#pragma unroll
        for (int i = 0; i < 8; i++) { int t = wtot[i]; wtot[i] = r; r += t; }
        wtot[8] = r;                       // tile total
    }
    __syncthreads();

    int texcl = wtot[w] + wexcl;
#pragma unroll
    for (int j = 0; j < 8; j++) {
        int idx = base + tid * 8 + j;
        if (idx < n) off[idx] = texcl + loc[j];
    }
    if (tid == 0) bsum[b] = wtot[8];
}

// step 2: scan the tile sums (<=64 per array). warp 0: tp, warp 1: int.
__global__ void k_scan_bsum(int nb, int n) {
    int w = threadIdx.x >> 5, lane = threadIdx.x & 31;
    int* bs  = w ? g_bsum_int : g_bsum_tp;
    int* off = w ? g_off_int  : g_off_tp;
    int base = 0;
    for (int i0 = 0; i0 < nb; i0 += 32) {
        int orig = (i0 + lane < nb) ? bs[i0 + lane] : 0;
        int v = orig;
#pragma unroll
        for (int d = 1; d < 32; d <<= 1) {
            int t = __shfl_up_sync(0xffffffffu, v, d);
            if (lane >= d) v += t;
        }
        if (i0 + lane < nb) bs[i0 + lane] = base + (v - orig);
        base += __shfl_sync(0xffffffffu, v, 31);
    }
    if (lane == 0) off[n] = base;
}

// step 3: add tile bases, materialize cur
__global__ void k_scan_add(int n) {
    int i = blockIdx.x * blockDim.x + threadIdx.x;
    if (i < n) {
        int b = i / TILE;
        int o = g_off_tp[i] + g_bsum_tp[b];
        g_off_tp[i] = o;  g_cur_tp[i] = o;
        int o2 = g_off_int[i] + g_bsum_int[b];
        g_off_int[i] = o2; g_cur_int[i] = o2;
    }
}

// ------------------------------------------------------------------
__global__ void k_fill(const int* __restrict__ tp_src,
                       const int* __restrict__ tp_dst,
                       const int* __restrict__ int_src,
                       const int* __restrict__ int_dst, int E) {
    int t = blockIdx.x * blockDim.x + threadIdx.x;
    if (t < E) {
        int pos = atomicAdd(&g_cur_tp[tp_dst[t]], 1);
        g_csr_tp[pos] = tp_src[t];
    } else if (t < 2 * E) {
        int e = t - E;
        int pos = atomicAdd(&g_cur_int[int_dst[e]], 1);
        g_csr_int[pos] = int_src[e];
    }
}

// ------------------------------------------------------------------
__global__ void k_transform6(const float* __restrict__ x,
                             const float* __restrict__ Wtp,
                             const float* __restrict__ Wint,
                             int n_node) {
    int t = blockIdx.x * blockDim.x + threadIdx.x;
    int node = t >> 5;
    int c = t & 31;
    if (node >= n_node) return;
    float a = 0.f, b = 0.f;
#pragma unroll
    for (int k = 0; k < 6; k++) {
        float xv = __ldg(&x[node * 6 + k]);
        a = fmaf(xv, __ldg(&Wtp[k * OC + c]), a);
        b = fmaf(xv, __ldg(&Wint[k * OC + c]), b);
    }
    g_y_tp[node * OC + c]  = a;
    g_y_int[node * OC + c] = b;
}

// ------------------------------------------------------------------
// gather-sum over CSR list: sum_j y[csr[j]*32 + c]. unroll 8 for MLP.
__device__ __forceinline__ float gather_sum(const int* __restrict__ csr,
                                            int beg, int end,
                                            const float* __restrict__ y,
                                            int c) {
    float acc = 0.f;
    for (int i = beg; i < end; i += 32) {
        int m = min(32, end - i);
        int sv = (c < m) ? __ldg(&csr[i + c]) : 0;
        int j = 0;
        for (; j + 8 <= m; j += 8) {
            int s0 = __shfl_sync(0xffffffffu, sv, j);
            int s1 = __shfl_sync(0xffffffffu, sv, j + 1);
            int s2 = __shfl_sync(0xffffffffu, sv, j + 2);
            int s3 = __shfl_sync(0xffffffffu, sv, j + 3);
            int s4 = __shfl_sync(0xffffffffu, sv, j + 4);
            int s5 = __shfl_sync(0xffffffffu, sv, j + 5);
            int s6 = __shfl_sync(0xffffffffu, sv, j + 6);
            int s7 = __shfl_sync(0xffffffffu, sv, j + 7);
            float v0 = __ldg(&y[s0 * OC + c]);
            float v1 = __ldg(&y[s1 * OC + c]);
            float v2 = __ldg(&y[s2 * OC + c]);
            float v3 = __ldg(&y[s3 * OC + c]);
            float v4 = __ldg(&y[s4 * OC + c]);
            float v5 = __ldg(&y[s5 * OC + c]);
            float v6 = __ldg(&y[s6 * OC + c]);
            float v7 = __ldg(&y[s7 * OC + c]);
            acc += ((v0 + v1) + (v2 + v3)) + ((v4 + v5) + (v6 + v7));
        }
        for (; j < m; j++) {
            int sj = __shfl_sync(0xffffffffu, sv, j);
            acc += __ldg(&y[sj * OC + c]);
        }
    }
    return acc;
}

// ------------------------------------------------------------------
__global__ void k_combine1(const float* __restrict__ x,
                           const float* __restrict__ Ws,
                           const float* __restrict__ b,
                           const float* __restrict__ Wres,
                           const float* __restrict__ Wtp2,
                           const float* __restrict__ Wint2,
                           int n_node) {
    __shared__ float sWtp[OC * OC];
    __shared__ float sWint[OC * OC];
    for (int i = threadIdx.x; i < OC * OC; i += blockDim.x) {
        sWtp[i]  = Wtp2[i];
        sWint[i] = Wint2[i];
    }
    __syncthreads();

    int t = blockIdx.x * blockDim.x + threadIdx.x;
    int node = t >> 5;
    int c = t & 31;
    if (node >= n_node) return;

    float m_tp  = gather_sum(g_csr_tp,  g_off_tp[node],  g_off_tp[node + 1],  g_y_tp,  c);
    float m_int = gather_sum(g_csr_int, g_off_int[node], g_off_int[node + 1], g_y_int, c)
                  * g_inv[node];

    float acc = __ldg(&b[c]);
#pragma unroll
    for (int k = 0; k < 6; k++) {
        float xv = __ldg(&x[node * 6 + k]);
        acc = fmaf(xv, __ldg(&Ws[k * OC + c]) + __ldg(&Wres[k * OC + c]), acc);
    }
    acc += m_tp + m_int;
    float h = fmaxf(acc, 0.f);
    int o = node * OC + c;
    g_h[o] = h;

    float atp = 0.f, ain = 0.f;
#pragma unroll
    for (int k = 0; k < OC; k++) {
        float hk = __shfl_sync(0xffffffffu, h, k);
        atp = fmaf(hk, sWtp[k * OC + c], atp);
        ain = fmaf(hk, sWint[k * OC + c], ain);
    }
    g_y_tp2[o]  = atp;
    g_y_int2[o] = ain;
}

// ------------------------------------------------------------------
__global__ void k_combine2(const float* __restrict__ Ws2,
                           const float* __restrict__ b2,
                           const float* __restrict__ Wd1,
                           const float* __restrict__ bd1,
                           const float* __restrict__ Wd2,
                           const float* __restrict__ bd2,
                           float* __restrict__ out,
                           int n_node) {
    __shared__ float sWs[OC * OC];
    __shared__ float sWd1[OC * OC];
    for (int i = threadIdx.x; i < OC * OC; i += blockDim.x) {
        sWs[i]  = Ws2[i];
        sWd1[i] = Wd1[i];
    }
    __syncthreads();

    int t = blockIdx.x * blockDim.x + threadIdx.x;
    int node = t >> 5;
    int c = t & 31;
    if (node >= n_node) return;

    float m_tp  = gather_sum(g_csr_tp,  g_off_tp[node],  g_off_tp[node + 1],  g_y_tp2,  c);
    float m_int = gather_sum(g_csr_int, g_off_int[node], g_off_int[node + 1], g_y_int2, c)
                  * g_inv[node];

    int o = node * OC + c;
    float h = g_h[o];
    float acc = __ldg(&b2[c]) + h;      // identity residual
#pragma unroll
    for (int k = 0; k < OC; k++) {
        float hk = __shfl_sync(0xffffffffu, h, k);
        acc = fmaf(hk, sWs[k * OC + c], acc);
    }
    acc += m_tp + m_int;
    float h2 = fmaxf(acc, 0.f);

    float d = __ldg(&bd1[c]);
#pragma unroll
    for (int k = 0; k < OC; k++) {
        float hk = __shfl_sync(0xffffffffu, h2, k);
        d = fmaf(hk, sWd1[k * OC + c], d);
    }
    d = fmaxf(d, 0.f) * __ldg(&Wd2[c]);

#pragma unroll
    for (int off = 16; off > 0; off >>= 1)
        d += __shfl_xor_sync(0xffffffffu, d, off);

    if (c == 0)
        out[node] = 1.f / (1.f + __expf(-(d + __ldg(&bd2[0]))));
}

// ------------------------------------------------------------------
extern "C" void kernel_launch(void* const* d_in, const int* in_sizes, int n_in,
                              void* d_out, int out_size) {
    const float* x        = (const float*)d_in[0];
    const int*   edge_tp  = (const int*)d_in[1];
    const int*   edge_int = (const int*)d_in[2];
    const float* W_self1  = (const float*)d_in[3];
    const float* b1       = (const float*)d_in[4];
    const float* W_tp1    = (const float*)d_in[5];
    const float* W_int1   = (const float*)d_in[6];
    const float* W_res1   = (const float*)d_in[7];
    const float* W_self2  = (const float*)d_in[8];
    const float* b2       = (const float*)d_in[9];
    const float* W_tp2    = (const float*)d_in[10];
    const float* W_int2   = (const float*)d_in[11];
    const float* Wd1      = (const float*)d_in[12];
    const float* bd1      = (const float*)d_in[13];
    const float* Wd2      = (const float*)d_in[14];
    const float* bd2      = (const float*)d_in[15];
    float* out = (float*)d_out;

    const int N = in_sizes[0] / 6;        // 100000
    const int E = in_sizes[1] / 2;        // 1600000

    const int* tp_src  = edge_tp;
    const int* tp_dst  = edge_tp + E;
    const int* int_src = edge_int;
    const int* int_dst = edge_int + E;

    const int TB = 256;
    const int gNode = (N * OC + TB - 1) / TB;
    const int gN    = (N + TB - 1) / TB;
    const int gE2   = (2 * E + TB - 1) / TB;
    const int nb    = (N + TILE - 1) / TILE;

    // CSR build (shared by both blocks)
    k_zero_cnt<<<gN, TB>>>(N);
    k_count<<<gE2, TB>>>(tp_dst, int_dst, E);
    k_scan_local<<<2 * nb, TB>>>(N, nb);
    k_scan_bsum<<<1, 64>>>(nb, N);
    k_scan_add<<<gN, TB>>>(N);
    k_fill<<<gE2, TB>>>(tp_src, tp_dst, int_src, int_dst, E);

    // block 1
    k_transform6<<<gNode, TB>>>(x, W_tp1, W_int1, N);
    k_combine1<<<gNode, TB>>>(x, W_self1, b1, W_res1, W_tp2, W_int2, N);

    // block 2 + decoder
    k_combine2<<<gNode, TB>>>(W_self2, b2, Wd1, bd1, Wd2, bd2, out, N);
}

// round 5
// speedup vs baseline: 2.4270x; 1.0051x over previous
#include <cuda_runtime.h>
#include <cuda_fp16.h>
#include <math.h>

#define OC 32
#define MAXN 100000
#define MAXE 1600000
#define TILE 2048
#define MAXB ((MAXN + TILE - 1) / TILE + 1)

// ---- scratch (device globals; referenced ONLY from device code) ----
// message arrays in fp16 (gather inputs; accumulation stays fp32)
__device__ __half g_y_tp  [MAXN * OC];
__device__ __half g_y_int [MAXN * OC];
__device__ __half g_y_tp2 [MAXN * OC];
__device__ __half g_y_int2[MAXN * OC];
__device__ float  g_h     [MAXN * OC];
__device__ float  g_inv   [MAXN];
__device__ int    g_cnt_tp [MAXN];
__device__ int    g_cnt_int[MAXN];
__device__ int    g_off_tp [MAXN + 1];
__device__ int    g_off_int[MAXN + 1];
__device__ int    g_cur_tp [MAXN];
__device__ int    g_cur_int[MAXN];
__device__ int    g_csr_tp [MAXE];
__device__ int    g_csr_int[MAXE];
__device__ int    g_bsum_tp [MAXB];
__device__ int    g_bsum_int[MAXB];

// ------------------------------------------------------------------
__global__ void k_zero_cnt(int n) {
    int i = blockIdx.x * blockDim.x + threadIdx.x;
    if (i < n) { g_cnt_tp[i] = 0; g_cnt_int[i] = 0; }
}

// degree count for both edge types, FUSED with block-1 transforms
// (count is atomic-latency bound at ~5% issue; the FMAs ride free).
__global__ void k_count_transform(const int* __restrict__ tp_dst,
                                  const int* __restrict__ int_dst,
                                  const float* __restrict__ x,
                                  const float* __restrict__ Wtp,
                                  const float* __restrict__ Wint,
                                  int E, int n_node) {
    int t = blockIdx.x * blockDim.x + threadIdx.x;
    if (t < E)          atomicAdd(&g_cnt_tp[tp_dst[t]], 1);
    else if (t < 2 * E) atomicAdd(&g_cnt_int[int_dst[t - E]], 1);

    if (t < n_node * OC) {
        int node = t >> 5;
        int c = t & 31;
        float a = 0.f, b = 0.f;
#pragma unroll
        for (int k = 0; k < 6; k++) {
            float xv = __ldg(&x[node * 6 + k]);
            a = fmaf(xv, __ldg(&Wtp[k * OC + c]), a);
            b = fmaf(xv, __ldg(&Wint[k * OC + c]), b);
        }
        g_y_tp[t]  = __float2half(a);
        g_y_int[t] = __float2half(b);
    }
}

// ------------------------------------------------------------------
// tiled scan, step 1: per-tile exclusive prefix + tile sums.
__global__ void k_scan_local(int n, int nb) {
    __shared__ int s[TILE];
    __shared__ int wtot[9];

    bool is_int = (blockIdx.x >= nb);
    int b = is_int ? blockIdx.x - nb : blockIdx.x;
    const int* __restrict__ cnt = is_int ? g_cnt_int : g_cnt_tp;
    int* __restrict__ off  = is_int ? g_off_int  : g_off_tp;
    int* __restrict__ bsum = is_int ? g_bsum_int : g_bsum_tp;

    int tid = threadIdx.x;
    int base = b * TILE;

#pragma unroll
    for (int k = 0; k < 8; k++) {
        int idx = base + k * 256 + tid;
        int v = (idx < n) ? cnt[idx] : 0;
        s[k * 256 + tid] = v;
        if (is_int && idx < n) g_inv[idx] = 1.f / fmaxf((float)v, 1.f);
    }
    __syncthreads();

    int loc[8];
    int tsum = 0;
#pragma unroll
    for (int j = 0; j < 8; j++) {
        int v = s[tid * 8 + j];
        loc[j] = tsum;
        tsum += v;
    }

    int lane = tid & 31, w = tid >> 5;
    int incl = tsum;
#pragma unroll
    for (int d = 1; d < 32; d <<= 1) {
        int t = __shfl_up_sync(0xffffffffu, incl, d);
        if (lane >= d) incl += t;
    }
    int wexcl = incl - tsum;
    if (lane == 31) wtot[w] = incl;
    __syncthreads();
    if (tid == 0) {
        int r = 0;
#pragma unroll
        for (int i = 0; i < 8; i++) { int t = wtot[i]; wtot[i] = r; r += t; }
        wtot[8] = r;
    }
    __syncthreads();

    int texcl = wtot[w] + wexcl;
#pragma unroll
    for (int j = 0; j < 8; j++) {
        int idx = base + tid * 8 + j;
        if (idx < n) off[idx] = texcl + loc[j];
    }
    if (tid == 0) bsum[b] = wtot[8];
}

// step 2: scan tile sums (<=49/array). warp 0: tp, warp 1: int.
__global__ void k_scan_bsum(int nb, int n) {
    int w = threadIdx.x >> 5, lane = threadIdx.x & 31;
    int* bs  = w ? g_bsum_int : g_bsum_tp;
    int* off = w ? g_off_int  : g_off_tp;
    int base = 0;
    for (int i0 = 0; i0 < nb; i0 += 32) {
        int orig = (i0 + lane < nb) ? bs[i0 + lane] : 0;
        int v = orig;
#pragma unroll
        for (int d = 1; d < 32; d <<= 1) {
            int t = __shfl_up_sync(0xffffffffu, v, d);
            if (lane >= d) v += t;
        }
        if (i0 + lane < nb) bs[i0 + lane] = base + (v - orig);
        base += __shfl_sync(0xffffffffu, v, 31);
    }
    if (lane == 0) off[n] = base;
}

// step 3: add tile bases, materialize cur
__global__ void k_scan_add(int n) {
    int i = blockIdx.x * blockDim.x + threadIdx.x;
    if (i < n) {
        int b = i / TILE;
        int o = g_off_tp[i] + g_bsum_tp[b];
        g_off_tp[i] = o;  g_cur_tp[i] = o;
        int o2 = g_off_int[i] + g_bsum_int[b];
        g_off_int[i] = o2; g_cur_int[i] = o2;
    }
}

// ------------------------------------------------------------------
__global__ void k_fill(const int* __restrict__ tp_src,
                       const int* __restrict__ tp_dst,
                       const int* __restrict__ int_src,
                       const int* __restrict__ int_dst, int E) {
    int t = blockIdx.x * blockDim.x + threadIdx.x;
    if (t < E) {
        int pos = atomicAdd(&g_cur_tp[tp_dst[t]], 1);
        g_csr_tp[pos] = tp_src[t];
    } else if (t < 2 * E) {
        int e = t - E;
        int pos = atomicAdd(&g_cur_int[int_dst[e]], 1);
        g_csr_int[pos] = int_src[e];
    }
}

// ------------------------------------------------------------------
// gather-sum over CSR list: sum_j (float)y[csr[j]*32 + c], unroll 8.
__device__ __forceinline__ float gather_sum(const int* __restrict__ csr,
                                            int beg, int end,
                                            const __half* __restrict__ y,
                                            int c) {
    float acc = 0.f;
    for (int i = beg; i < end; i += 32) {
        int m = min(32, end - i);
        int sv = (c < m) ? __ldg(&csr[i + c]) : 0;
        int j = 0;
        for (; j + 8 <= m; j += 8) {
            int s0 = __shfl_sync(0xffffffffu, sv, j);
            int s1 = __shfl_sync(0xffffffffu, sv, j + 1);
            int s2 = __shfl_sync(0xffffffffu, sv, j + 2);
            int s3 = __shfl_sync(0xffffffffu, sv, j + 3);
            int s4 = __shfl_sync(0xffffffffu, sv, j + 4);
            int s5 = __shfl_sync(0xffffffffu, sv, j + 5);
            int s6 = __shfl_sync(0xffffffffu, sv, j + 6);
            int s7 = __shfl_sync(0xffffffffu, sv, j + 7);
            float v0 = __half2float(__ldg(&y[s0 * OC + c]));
            float v1 = __half2float(__ldg(&y[s1 * OC + c]));
            float v2 = __half2float(__ldg(&y[s2 * OC + c]));
            float v3 = __half2float(__ldg(&y[s3 * OC + c]));
            float v4 = __half2float(__ldg(&y[s4 * OC + c]));
            float v5 = __half2float(__ldg(&y[s5 * OC + c]));
            float v6 = __half2float(__ldg(&y[s6 * OC + c]));
            float v7 = __half2float(__ldg(&y[s7 * OC + c]));
            acc += ((v0 + v1) + (v2 + v3)) + ((v4 + v5) + (v6 + v7));
        }
        for (; j < m; j++) {
            int sj = __shfl_sync(0xffffffffu, sv, j);
            acc += __half2float(__ldg(&y[sj * OC + c]));
        }
    }
    return acc;
}

// ------------------------------------------------------------------
__global__ void k_combine1(const float* __restrict__ x,
                           const float* __restrict__ Ws,
                           const float* __restrict__ b,
                           const float* __restrict__ Wres,
                           const float* __restrict__ Wtp2,
                           const float* __restrict__ Wint2,
                           int n_node) {
    __shared__ float sWtp[OC * OC];
    __shared__ float sWint[OC * OC];
    for (int i = threadIdx.x; i < OC * OC; i += blockDim.x) {
        sWtp[i]  = Wtp2[i];
        sWint[i] = Wint2[i];
    }
    __syncthreads();

    int t = blockIdx.x * blockDim.x + threadIdx.x;
    int node = t >> 5;
    int c = t & 31;
    if (node >= n_node) return;

    float m_tp  = gather_sum(g_csr_tp,  g_off_tp[node],  g_off_tp[node + 1],  g_y_tp,  c);
    float m_int = gather_sum(g_csr_int, g_off_int[node], g_off_int[node + 1], g_y_int, c)
                  * g_inv[node];

    float acc = __ldg(&b[c]);
#pragma unroll
    for (int k = 0; k < 6; k++) {
        float xv = __ldg(&x[node * 6 + k]);
        acc = fmaf(xv, __ldg(&Ws[k * OC + c]) + __ldg(&Wres[k * OC + c]), acc);
    }
    acc += m_tp + m_int;
    float h = fmaxf(acc, 0.f);
    int o = node * OC + c;
    g_h[o] = h;

    float atp = 0.f, ain = 0.f;
#pragma unroll
    for (int k = 0; k < OC; k++) {
        float hk = __shfl_sync(0xffffffffu, h, k);
        atp = fmaf(hk, sWtp[k * OC + c], atp);
        ain = fmaf(hk, sWint[k * OC + c], ain);
    }
    g_y_tp2[o]  = __float2half(atp);
    g_y_int2[o] = __float2half(ain);
}

// ------------------------------------------------------------------
__global__ void k_combine2(const float* __restrict__ Ws2,
                           const float* __restrict__ b2,
                           const float* __restrict__ Wd1,
                           const float* __restrict__ bd1,
                           const float* __restrict__ Wd2,
                           const float* __restrict__ bd2,
                           float* __restrict__ out,
                           int n_node) {
    __shared__ float sWs[OC * OC];
    __shared__ float sWd1[OC * OC];
    for (int i = threadIdx.x; i < OC * OC; i += blockDim.x) {
        sWs[i]  = Ws2[i];
        sWd1[i] = Wd1[i];
    }
    __syncthreads();

    int t = blockIdx.x * blockDim.x + threadIdx.x;
    int node = t >> 5;
    int c = t & 31;
    if (node >= n_node) return;

    float m_tp  = gather_sum(g_csr_tp,  g_off_tp[node],  g_off_tp[node + 1],  g_y_tp2,  c);
    float m_int = gather_sum(g_csr_int, g_off_int[node], g_off_int[node + 1], g_y_int2, c)
                  * g_inv[node];

    int o = node * OC + c;
    float h = g_h[o];
    float acc = __ldg(&b2[c]) + h;      // identity residual
#pragma unroll
    for (int k = 0; k < OC; k++) {
        float hk = __shfl_sync(0xffffffffu, h, k);
        acc = fmaf(hk, sWs[k * OC + c], acc);
    }
    acc += m_tp + m_int;
    float h2 = fmaxf(acc, 0.f);

    float d = __ldg(&bd1[c]);
#pragma unroll
    for (int k = 0; k < OC; k++) {
        float hk = __shfl_sync(0xffffffffu, h2, k);
        d = fmaf(hk, sWd1[k * OC + c], d);
    }
    d = fmaxf(d, 0.f) * __ldg(&Wd2[c]);

#pragma unroll
    for (int off = 16; off > 0; off >>= 1)
        d += __shfl_xor_sync(0xffffffffu, d, off);

    if (c == 0)
        out[node] = 1.f / (1.f + __expf(-(d + __ldg(&bd2[0]))));
}

// ------------------------------------------------------------------
extern "C" void kernel_launch(void* const* d_in, const int* in_sizes, int n_in,
                              void* d_out, int out_size) {
    const float* x        = (const float*)d_in[0];
    const int*   edge_tp  = (const int*)d_in[1];
    const int*   edge_int = (const int*)d_in[2];
    const float* W_self1  = (const float*)d_in[3];
    const float* b1       = (const float*)d_in[4];
    const float* W_tp1    = (const float*)d_in[5];
    const float* W_int1   = (const float*)d_in[6];
    const float* W_res1   = (const float*)d_in[7];
    const float* W_self2  = (const float*)d_in[8];
    const float* b2       = (const float*)d_in[9];
    const float* W_tp2    = (const float*)d_in[10];
    const float* W_int2   = (const float*)d_in[11];
    const float* Wd1      = (const float*)d_in[12];
    const float* bd1      = (const float*)d_in[13];
    const float* Wd2      = (const float*)d_in[14];
    const float* bd2      = (const float*)d_in[15];
    float* out = (float*)d_out;

    const int N = in_sizes[0] / 6;        // 100000
    const int E = in_sizes[1] / 2;        // 1600000

    const int* tp_src  = edge_tp;
    const int* tp_dst  = edge_tp + E;
    const int* int_src = edge_int;
    const int* int_dst = edge_int + E;

    const int TB = 256;
    const int gNode = (N * OC + TB - 1) / TB;
    const int gN    = (N + TB - 1) / TB;
    long long work  = (long long)2 * E;
    if ((long long)N * OC > work) work = (long long)N * OC;
    const int gBig  = (int)((work + TB - 1) / TB);
    const int gE2   = (2 * E + TB - 1) / TB;
    const int nb    = (N + TILE - 1) / TILE;

    // CSR build (shared by both blocks); block-1 transform fused into count
    k_zero_cnt<<<gN, TB>>>(N);
    k_count_transform<<<gBig, TB>>>(tp_dst, int_dst, x, W_tp1, W_int1, E, N);
    k_scan_local<<<2 * nb, TB>>>(N, nb);
    k_scan_bsum<<<1, 64>>>(nb, N);
    k_scan_add<<<gN, TB>>>(N);
    k_fill<<<gE2, TB>>>(tp_src, tp_dst, int_src, int_dst, E);

    // block 1 combine (+ block-2 transforms)
    k_combine1<<<gNode, TB>>>(x, W_self1, b1, W_res1, W_tp2, W_int2, N);

    // block 2 combine + decoder
    k_combine2<<<gNode, TB>>>(W_self2, b2, Wd1, bd1, Wd2, bd2, out, N);
}

// round 6
// speedup vs baseline: 2.5227x; 1.0394x over previous
#include <cuda_runtime.h>
#include <cuda_fp16.h>
#include <math.h>

#define OC 32
#define MAXN 100000
#define MAXE 1600000
#define TILE 2048
#define NB   ((MAXN + TILE - 1) / TILE)   // 49 tiles per array

// ---- scratch (device globals; referenced ONLY from device code) ----
// message arrays in fp16 (gather inputs; accumulation stays fp32)
__device__ __half g_y_tp  [MAXN * OC];
__device__ __half g_y_int [MAXN * OC];
__device__ __half g_y_tp2 [MAXN * OC];
__device__ __half g_y_int2[MAXN * OC];
__device__ float  g_h     [MAXN * OC];
__device__ float  g_inv   [MAXN];
__device__ int    g_cnt_tp [MAXN];      // zero at start of every replay:
__device__ int    g_cnt_int[MAXN];      // .bss-zero first, scan re-zeroes after read
__device__ int    g_off_tp [MAXN + 1];
__device__ int    g_off_int[MAXN + 1];
__device__ int    g_cur_tp [MAXN];
__device__ int    g_cur_int[MAXN];
__device__ int    g_csr_tp [MAXE];
__device__ int    g_csr_int[MAXE];
__device__ unsigned g_look_tp [NB];     // decoupled-lookback words; zeroed by k_fill
__device__ unsigned g_look_int[NB];     // for the NEXT replay (.bss-zero first time)

// ------------------------------------------------------------------
// degree count for both edge types, FUSED with block-1 transforms.
__global__ void k_count_transform(const int* __restrict__ tp_dst,
                                  const int* __restrict__ int_dst,
                                  const float* __restrict__ x,
                                  const float* __restrict__ Wtp,
                                  const float* __restrict__ Wint,
                                  int E, int n_node) {
    int t = blockIdx.x * blockDim.x + threadIdx.x;
    if (t < E)          atomicAdd(&g_cnt_tp[tp_dst[t]], 1);
    else if (t < 2 * E) atomicAdd(&g_cnt_int[int_dst[t - E]], 1);

    if (t < n_node * OC) {
        int node = t >> 5;
        int c = t & 31;
        float a = 0.f, b = 0.f;
#pragma unroll
        for (int k = 0; k < 6; k++) {
            float xv = __ldg(&x[node * 6 + k]);
            a = fmaf(xv, __ldg(&Wtp[k * OC + c]), a);
            b = fmaf(xv, __ldg(&Wint[k * OC + c]), b);
        }
        g_y_tp[t]  = __float2half(a);
        g_y_int[t] = __float2half(b);
    }
}

// ------------------------------------------------------------------
// single-pass decoupled-lookback scan. grid = 2*nb (<148: all resident,
// no deadlock). blocks [0,nb) -> tp, [nb,2nb) -> int (+ inv).
// Packed protocol word: flag(2b)<<30 | value(30b); totals < 2^30.
#define FLG_AGG 1u
#define FLG_PRE 2u

__global__ void k_scan(int n, int nb) {
    __shared__ int s[TILE];
    __shared__ int wtot[9];
    __shared__ int s_base;

    bool is_int = (blockIdx.x >= nb);
    int b = is_int ? blockIdx.x - nb : blockIdx.x;
    int* __restrict__ cnt = is_int ? g_cnt_int : g_cnt_tp;
    int* __restrict__ off = is_int ? g_off_int : g_off_tp;
    int* __restrict__ cur = is_int ? g_cur_int : g_cur_tp;
    unsigned* look = is_int ? g_look_int : g_look_tp;

    int tid = threadIdx.x;
    int lane = tid & 31, w = tid >> 5;
    int base0 = b * TILE;

    // coalesced load; self-clean cnt for next replay; int side writes inv
#pragma unroll
    for (int k = 0; k < 8; k++) {
        int idx = base0 + k * 256 + tid;
        int v = 0;
        if (idx < n) {
            v = cnt[idx];
            cnt[idx] = 0;
            if (is_int) g_inv[idx] = 1.f / fmaxf((float)v, 1.f);
        }
        s[k * 256 + tid] = v;
    }
    __syncthreads();

    // per-thread blocked exclusive prefix
    int loc[8];
    int tsum = 0;
#pragma unroll
    for (int j = 0; j < 8; j++) {
        int v = s[tid * 8 + j];
        loc[j] = tsum;
        tsum += v;
    }
    // warp inclusive scan
    int incl = tsum;
#pragma unroll
    for (int d = 1; d < 32; d <<= 1) {
        int t = __shfl_up_sync(0xffffffffu, incl, d);
        if (lane >= d) incl += t;
    }
    int wexcl = incl - tsum;
    if (lane == 31) wtot[w] = incl;
    __syncthreads();
    if (tid == 0) {
        int r = 0;
#pragma unroll
        for (int i = 0; i < 8; i++) { int t = wtot[i]; wtot[i] = r; r += t; }
        wtot[8] = r;                     // tile total
    }
    __syncthreads();
    int total = wtot[8];
    int texcl = wtot[w] + wexcl;

    // publish + warp-parallel lookback (warp 0)
    if (w == 0) {
        if (lane == 0) {
            unsigned word = (b == 0) ? ((FLG_PRE << 30) | (unsigned)total)
                                     : ((FLG_AGG << 30) | (unsigned)total);
            atomicExch(&look[b], word);
        }
        __syncwarp();
        int running = 0;
        if (b > 0) {
            int p = b - 1;
            while (true) {
                int idx = p - lane;                     // lane 0 = closest
                unsigned wv = 0;
                if (idx >= 0) {
                    volatile unsigned* ptr = &look[idx];
                    do { wv = *ptr; } while ((wv >> 30) == 0);
                }
                unsigned flag = wv >> 30;
                int val = (int)(wv & 0x3FFFFFFFu);
                unsigned pmask = __ballot_sync(0xffffffffu, flag == FLG_PRE);
                int stop = pmask ? (__ffs(pmask) - 1) : 32;
                int contrib = (idx >= 0 && lane <= stop) ? val : 0;
#pragma unroll
                for (int o = 16; o > 0; o >>= 1)
                    contrib += __shfl_xor_sync(0xffffffffu, contrib, o);
                running += contrib;
                if (pmask) break;
                p -= 32;                                 // next window (b==0 has PRE)
            }
            if (lane == 0)
                atomicExch(&look[b], (FLG_PRE << 30) | (unsigned)(running + total));
        }
        if (lane == 0) s_base = running;
    }
    __syncthreads();
    int base = s_base;

    // write off / cur
#pragma unroll
    for (int j = 0; j < 8; j++) {
        int idx = base0 + tid * 8 + j;
        if (idx < n) {
            int o = base + texcl + loc[j];
            off[idx] = o;
            cur[idx] = o;
        }
    }
    if (tid == 0 && b == nb - 1) off[n] = base + total;
}

// ------------------------------------------------------------------
__global__ void k_fill(const int* __restrict__ tp_src,
                       const int* __restrict__ tp_dst,
                       const int* __restrict__ int_src,
                       const int* __restrict__ int_dst, int E) {
    int t = blockIdx.x * blockDim.x + threadIdx.x;
    if (t < NB) { g_look_tp[t] = 0; g_look_int[t] = 0; }   // clean for next replay
    if (t < E) {
        int pos = atomicAdd(&g_cur_tp[tp_dst[t]], 1);
        g_csr_tp[pos] = tp_src[t];
    } else if (t < 2 * E) {
        int e = t - E;
        int pos = atomicAdd(&g_cur_int[int_dst[e]], 1);
        g_csr_int[pos] = int_src[e];
    }
}

// ------------------------------------------------------------------
// gather-sum over CSR list: sum_j (float)y[csr[j]*32 + c], unroll 8.
__device__ __forceinline__ float gather_sum(const int* __restrict__ csr,
                                            int beg, int end,
                                            const __half* __restrict__ y,
                                            int c) {
    float acc = 0.f;
    for (int i = beg; i < end; i += 32) {
        int m = min(32, end - i);
        int sv = (c < m) ? __ldg(&csr[i + c]) : 0;
        int j = 0;
        for (; j + 8 <= m; j += 8) {
            int s0 = __shfl_sync(0xffffffffu, sv, j);
            int s1 = __shfl_sync(0xffffffffu, sv, j + 1);
            int s2 = __shfl_sync(0xffffffffu, sv, j + 2);
            int s3 = __shfl_sync(0xffffffffu, sv, j + 3);
            int s4 = __shfl_sync(0xffffffffu, sv, j + 4);
            int s5 = __shfl_sync(0xffffffffu, sv, j + 5);
            int s6 = __shfl_sync(0xffffffffu, sv, j + 6);
            int s7 = __shfl_sync(0xffffffffu, sv, j + 7);
            float v0 = __half2float(__ldg(&y[s0 * OC + c]));
            float v1 = __half2float(__ldg(&y[s1 * OC + c]));
            float v2 = __half2float(__ldg(&y[s2 * OC + c]));
            float v3 = __half2float(__ldg(&y[s3 * OC + c]));
            float v4 = __half2float(__ldg(&y[s4 * OC + c]));
            float v5 = __half2float(__ldg(&y[s5 * OC + c]));
            float v6 = __half2float(__ldg(&y[s6 * OC + c]));
            float v7 = __half2float(__ldg(&y[s7 * OC + c]));
            acc += ((v0 + v1) + (v2 + v3)) + ((v4 + v5) + (v6 + v7));
        }
        for (; j < m; j++) {
            int sj = __shfl_sync(0xffffffffu, sv, j);
            acc += __half2float(__ldg(&y[sj * OC + c]));
        }
    }
    return acc;
}

// ------------------------------------------------------------------
__global__ void k_combine1(const float* __restrict__ x,
                           const float* __restrict__ Ws,
                           const float* __restrict__ b,
                           const float* __restrict__ Wres,
                           const float* __restrict__ Wtp2,
                           const float* __restrict__ Wint2,
                           int n_node) {
    __shared__ float sWtp[OC * OC];
    __shared__ float sWint[OC * OC];
    for (int i = threadIdx.x; i < OC * OC; i += blockDim.x) {
        sWtp[i]  = Wtp2[i];
        sWint[i] = Wint2[i];
    }
    __syncthreads();

    int t = blockIdx.x * blockDim.x + threadIdx.x;
    int node = t >> 5;
    int c = t & 31;
    if (node >= n_node) return;

    float m_tp  = gather_sum(g_csr_tp,  g_off_tp[node],  g_off_tp[node + 1],  g_y_tp,  c);
    float m_int = gather_sum(g_csr_int, g_off_int[node], g_off_int[node + 1], g_y_int, c)
                  * g_inv[node];

    float acc = __ldg(&b[c]);
#pragma unroll
    for (int k = 0; k < 6; k++) {
        float xv = __ldg(&x[node * 6 + k]);
        acc = fmaf(xv, __ldg(&Ws[k * OC + c]) + __ldg(&Wres[k * OC + c]), acc);
    }
    acc += m_tp + m_int;
    float h = fmaxf(acc, 0.f);
    int o = node * OC + c;
    g_h[o] = h;

    float atp = 0.f, ain = 0.f;
#pragma unroll
    for (int k = 0; k < OC; k++) {
        float hk = __shfl_sync(0xffffffffu, h, k);
        atp = fmaf(hk, sWtp[k * OC + c], atp);
        ain = fmaf(hk, sWint[k * OC + c], ain);
    }
    g_y_tp2[o]  = __float2half(atp);
    g_y_int2[o] = __float2half(ain);
}

// ------------------------------------------------------------------
__global__ void k_combine2(const float* __restrict__ Ws2,
                           const float* __restrict__ b2,
                           const float* __restrict__ Wd1,
                           const float* __restrict__ bd1,
                           const float* __restrict__ Wd2,
                           const float* __restrict__ bd2,
                           float* __restrict__ out,
                           int n_node) {
    __shared__ float sWs[OC * OC];
    __shared__ float sWd1[OC * OC];
    for (int i = threadIdx.x; i < OC * OC; i += blockDim.x) {
        sWs[i]  = Ws2[i];
        sWd1[i] = Wd1[i];
    }
    __syncthreads();

    int t = blockIdx.x * blockDim.x + threadIdx.x;
    int node = t >> 5;
    int c = t & 31;
    if (node >= n_node) return;

    float m_tp  = gather_sum(g_csr_tp,  g_off_tp[node],  g_off_tp[node + 1],  g_y_tp2,  c);
    float m_int = gather_sum(g_csr_int, g_off_int[node], g_off_int[node + 1], g_y_int2, c)
                  * g_inv[node];

    int o = node * OC + c;
    float h = g_h[o];
    float acc = __ldg(&b2[c]) + h;      // identity residual
#pragma unroll
    for (int k = 0; k < OC; k++) {
        float hk = __shfl_sync(0xffffffffu, h, k);
        acc = fmaf(hk, sWs[k * OC + c], acc);
    }
    acc += m_tp + m_int;
    float h2 = fmaxf(acc, 0.f);

    float d = __ldg(&bd1[c]);
#pragma unroll
    for (int k = 0; k < OC; k++) {
        float hk = __shfl_sync(0xffffffffu, h2, k);
        d = fmaf(hk, sWd1[k * OC + c], d);
    }
    d = fmaxf(d, 0.f) * __ldg(&Wd2[c]);

#pragma unroll
    for (int off = 16; off > 0; off >>= 1)
        d += __shfl_xor_sync(0xffffffffu, d, off);

    if (c == 0)
        out[node] = 1.f / (1.f + __expf(-(d + __ldg(&bd2[0]))));
}

// ------------------------------------------------------------------
extern "C" void kernel_launch(void* const* d_in, const int* in_sizes, int n_in,
                              void* d_out, int out_size) {
    const float* x        = (const float*)d_in[0];
    const int*   edge_tp  = (const int*)d_in[1];
    const int*   edge_int = (const int*)d_in[2];
    const float* W_self1  = (const float*)d_in[3];
    const float* b1       = (const float*)d_in[4];
    const float* W_tp1    = (const float*)d_in[5];
    const float* W_int1   = (const float*)d_in[6];
    const float* W_res1   = (const float*)d_in[7];
    const float* W_self2  = (const float*)d_in[8];
    const float* b2       = (const float*)d_in[9];
    const float* W_tp2    = (const float*)d_in[10];
    const float* W_int2   = (const float*)d_in[11];
    const float* Wd1      = (const float*)d_in[12];
    const float* bd1      = (const float*)d_in[13];
    const float* Wd2      = (const float*)d_in[14];
    const float* bd2      = (const float*)d_in[15];
    float* out = (float*)d_out;

    const int N = in_sizes[0] / 6;        // 100000
    const int E = in_sizes[1] / 2;        // 1600000

    const int* tp_src  = edge_tp;
    const int* tp_dst  = edge_tp + E;
    const int* int_src = edge_int;
    const int* int_dst = edge_int + E;

    const int TB = 256;
    const int gNode = (N * OC + TB - 1) / TB;
    long long work  = (long long)2 * E;
    if ((long long)N * OC > work) work = (long long)N * OC;
    const int gBig  = (int)((work + TB - 1) / TB);
    const int gE2   = (2 * E + TB - 1) / TB;
    const int nb    = (N + TILE - 1) / TILE;

    // 5-launch pipeline (combine1 = launch index 3 -> gets profiled)
    k_count_transform<<<gBig, TB>>>(tp_dst, int_dst, x, W_tp1, W_int1, E, N);
    k_scan<<<2 * nb, TB>>>(N, nb);
    k_fill<<<gE2, TB>>>(tp_src, tp_dst, int_src, int_dst, E);
    k_combine1<<<gNode, TB>>>(x, W_self1, b1, W_res1, W_tp2, W_int2, N);
    k_combine2<<<gNode, TB>>>(W_self2, b2, Wd1, bd1, Wd2, bd2, out, N);
}

// round 7
// speedup vs baseline: 2.7284x; 1.0815x over previous
#include <cuda_runtime.h>
#include <cuda_fp16.h>
#include <math.h>

#define OC 32
#define MAXN 100000
#define MAXE 1600000
#define TILE 2048
#define NB   ((MAXN + TILE - 1) / TILE)   // 49 tiles per array
#define FULL 0xffffffffu

// ---- scratch (device globals; referenced ONLY from device code) ----
__device__ __half g_y_tp  [MAXN * OC];
__device__ __half g_y_int [MAXN * OC];
__device__ __half g_y_tp2 [MAXN * OC];
__device__ __half g_y_int2[MAXN * OC];
__device__ float  g_h     [MAXN * OC];
__device__ float  g_inv   [MAXN];
__device__ int    g_cnt_tp [MAXN];      // zeroed by scan after read (.bss first time)
__device__ int    g_cnt_int[MAXN];
__device__ int    g_off_tp [MAXN + 1];
__device__ int    g_off_int[MAXN + 1];
__device__ int    g_cur_tp [MAXN];
__device__ int    g_cur_int[MAXN];
__device__ int    g_csr_tp [MAXE];
__device__ int    g_csr_int[MAXE];
__device__ unsigned g_look_tp [NB];     // lookback flags; zeroed by k_fill for next replay
__device__ unsigned g_look_int[NB];

// ------------------------------------------------------------------
// degree count for both edge types, FUSED with block-1 transforms.
__global__ void k_count_transform(const int* __restrict__ tp_dst,
                                  const int* __restrict__ int_dst,
                                  const float* __restrict__ x,
                                  const float* __restrict__ Wtp,
                                  const float* __restrict__ Wint,
                                  int E, int n_node) {
    int t = blockIdx.x * blockDim.x + threadIdx.x;
    if (t < E)          atomicAdd(&g_cnt_tp[tp_dst[t]], 1);
    else if (t < 2 * E) atomicAdd(&g_cnt_int[int_dst[t - E]], 1);

    if (t < n_node * OC) {
        int node = t >> 5;
        int c = t & 31;
        float a = 0.f, b = 0.f;
#pragma unroll
        for (int k = 0; k < 6; k++) {
            float xv = __ldg(&x[node * 6 + k]);
            a = fmaf(xv, __ldg(&Wtp[k * OC + c]), a);
            b = fmaf(xv, __ldg(&Wint[k * OC + c]), b);
        }
        g_y_tp[t]  = __float2half(a);
        g_y_int[t] = __float2half(b);
    }
}

// ------------------------------------------------------------------
// single-pass decoupled-lookback scan (grid 2*nb < 148 -> all resident).
#define FLG_AGG 1u
#define FLG_PRE 2u

__global__ void k_scan(int n, int nb) {
    __shared__ int s[TILE];
    __shared__ int wtot[9];
    __shared__ int s_base;

    bool is_int = (blockIdx.x >= nb);
    int b = is_int ? blockIdx.x - nb : blockIdx.x;
    int* __restrict__ cnt = is_int ? g_cnt_int : g_cnt_tp;
    int* __restrict__ off = is_int ? g_off_int : g_off_tp;
    int* __restrict__ cur = is_int ? g_cur_int : g_cur_tp;
    unsigned* look = is_int ? g_look_int : g_look_tp;

    int tid = threadIdx.x;
    int lane = tid & 31, w = tid >> 5;
    int base0 = b * TILE;

#pragma unroll
    for (int k = 0; k < 8; k++) {
        int idx = base0 + k * 256 + tid;
        int v = 0;
        if (idx < n) {
            v = cnt[idx];
            cnt[idx] = 0;
            if (is_int) g_inv[idx] = 1.f / fmaxf((float)v, 1.f);
        }
        s[k * 256 + tid] = v;
    }
    __syncthreads();

    int loc[8];
    int tsum = 0;
#pragma unroll
    for (int j = 0; j < 8; j++) {
        int v = s[tid * 8 + j];
        loc[j] = tsum;
        tsum += v;
    }
    int incl = tsum;
#pragma unroll
    for (int d = 1; d < 32; d <<= 1) {
        int t = __shfl_up_sync(FULL, incl, d);
        if (lane >= d) incl += t;
    }
    int wexcl = incl - tsum;
    if (lane == 31) wtot[w] = incl;
    __syncthreads();
    if (tid == 0) {
        int r = 0;
#pragma unroll
        for (int i = 0; i < 8; i++) { int t = wtot[i]; wtot[i] = r; r += t; }
        wtot[8] = r;
    }
    __syncthreads();
    int total = wtot[8];
    int texcl = wtot[w] + wexcl;

    if (w == 0) {
        if (lane == 0) {
            unsigned word = (b == 0) ? ((FLG_PRE << 30) | (unsigned)total)
                                     : ((FLG_AGG << 30) | (unsigned)total);
            atomicExch(&look[b], word);
        }
        __syncwarp();
        int running = 0;
        if (b > 0) {
            int p = b - 1;
            while (true) {
                int idx = p - lane;
                unsigned wv = 0;
                if (idx >= 0) {
                    volatile unsigned* ptr = &look[idx];
                    do { wv = *ptr; } while ((wv >> 30) == 0);
                }
                unsigned flag = wv >> 30;
                int val = (int)(wv & 0x3FFFFFFFu);
                unsigned pmask = __ballot_sync(FULL, flag == FLG_PRE);
                int stop = pmask ? (__ffs(pmask) - 1) : 32;
                int contrib = (idx >= 0 && lane <= stop) ? val : 0;
#pragma unroll
                for (int o = 16; o > 0; o >>= 1)
                    contrib += __shfl_xor_sync(FULL, contrib, o);
                running += contrib;
                if (pmask) break;
                p -= 32;
            }
            if (lane == 0)
                atomicExch(&look[b], (FLG_PRE << 30) | (unsigned)(running + total));
        }
        if (lane == 0) s_base = running;
    }
    __syncthreads();
    int base = s_base;

#pragma unroll
    for (int j = 0; j < 8; j++) {
        int idx = base0 + tid * 8 + j;
        if (idx < n) {
            int o = base + texcl + loc[j];
            off[idx] = o;
            cur[idx] = o;
        }
    }
    if (tid == 0 && b == nb - 1) off[n] = base + total;
}

// ------------------------------------------------------------------
__global__ void k_fill(const int* __restrict__ tp_src,
                       const int* __restrict__ tp_dst,
                       const int* __restrict__ int_src,
                       const int* __restrict__ int_dst, int E) {
    int t = blockIdx.x * blockDim.x + threadIdx.x;
    if (t < NB) { g_look_tp[t] = 0; g_look_int[t] = 0; }   // clean for next replay
    if (t < E) {
        int pos = atomicAdd(&g_cur_tp[tp_dst[t]], 1);
        g_csr_tp[pos] = tp_src[t];
    } else if (t < 2 * E) {
        int e = t - E;
        int pos = atomicAdd(&g_cur_int[int_dst[e]], 1);
        g_csr_int[pos] = int_src[e];
    }
}

// ------------------------------------------------------------------
// pair-gather: one warp LDG.32(half2) covers TWO edges (lanes 0-15 edge j,
// lanes 16-31 edge j+1). Accumulates float2 for channel-pair m = lane&15.
__device__ __forceinline__ float2 gather_pair(const int* __restrict__ csr,
                                              int beg, int end,
                                              const __half2* __restrict__ y2,
                                              int lane) {
    int m = lane & 15;
    int hi = lane >> 4;                 // which edge of the pair this lane serves
    float acx = 0.f, acy = 0.f;
    for (int i = beg; i < end; i += 32) {
        int cnt = min(32, end - i);
        int sv = (lane < cnt) ? __ldg(&csr[i + lane]) : 0;
        int j = 0;
        for (; j + 8 <= cnt; j += 8) {  // 4 pairs in flight
            int s0 = __shfl_sync(FULL, sv, j     + hi);
            int s1 = __shfl_sync(FULL, sv, j + 2 + hi);
            int s2 = __shfl_sync(FULL, sv, j + 4 + hi);
            int s3 = __shfl_sync(FULL, sv, j + 6 + hi);
            float2 f0 = __half22float2(__ldg(&y2[s0 * 16 + m]));
            float2 f1 = __half22float2(__ldg(&y2[s1 * 16 + m]));
            float2 f2 = __half22float2(__ldg(&y2[s2 * 16 + m]));
            float2 f3 = __half22float2(__ldg(&y2[s3 * 16 + m]));
            acx += (f0.x + f1.x) + (f2.x + f3.x);
            acy += (f0.y + f1.y) + (f2.y + f3.y);
        }
        for (; j < cnt; j += 2) {       // tail (<=3 pairs, possibly ragged)
            int idx = j + hi;
            bool valid = idx < cnt;
            int s = __shfl_sync(FULL, sv, valid ? idx : j);
            float2 f = __half22float2(__ldg(&y2[s * 16 + m]));
            if (valid) { acx += f.x; acy += f.y; }
        }
    }
    return make_float2(acx, acy);
}

// fold pair-accumulators back to lane=channel layout (4 shfl per list)
__device__ __forceinline__ float pair_to_lane(float2 acc, int c) {
    float ax = acc.x + __shfl_xor_sync(FULL, acc.x, 16);
    float ay = acc.y + __shfl_xor_sync(FULL, acc.y, 16);
    float vx = __shfl_sync(FULL, ax, c >> 1);
    float vy = __shfl_sync(FULL, ay, c >> 1);
    return (c & 1) ? vy : vx;
}

// ------------------------------------------------------------------
// combine block 1 + block-2 transforms. warp/node, lane=channel.
// weights staged as k-pair-packed float2 -> LDS.64, shared h broadcasts.
__global__ void k_combine1(const float* __restrict__ x,
                           const float* __restrict__ Ws,
                           const float* __restrict__ b,
                           const float* __restrict__ Wres,
                           const float* __restrict__ Wtp2,
                           const float* __restrict__ Wint2,
                           int n_node) {
    __shared__ float2 sWtp[16 * 32];
    __shared__ float2 sWint[16 * 32];
    for (int i = threadIdx.x; i < 16 * 32; i += blockDim.x) {
        int p = i >> 5, cc = i & 31;
        sWtp[i]  = make_float2(Wtp2[(2 * p) * OC + cc],  Wtp2[(2 * p + 1) * OC + cc]);
        sWint[i] = make_float2(Wint2[(2 * p) * OC + cc], Wint2[(2 * p + 1) * OC + cc]);
    }
    __syncthreads();

    int t = blockIdx.x * blockDim.x + threadIdx.x;
    int node = t >> 5;
    int c = t & 31;
    if (node >= n_node) return;

    float2 a_tp  = gather_pair(g_csr_tp,  g_off_tp[node],  g_off_tp[node + 1],
                               (const __half2*)g_y_tp,  c);
    float2 a_int = gather_pair(g_csr_int, g_off_int[node], g_off_int[node + 1],
                               (const __half2*)g_y_int, c);
    float m_tp  = pair_to_lane(a_tp, c);
    float m_int = pair_to_lane(a_int, c) * g_inv[node];

    float acc = __ldg(&b[c]);
#pragma unroll
    for (int k = 0; k < 6; k++) {
        float xv = __ldg(&x[node * 6 + k]);
        acc = fmaf(xv, __ldg(&Ws[k * OC + c]) + __ldg(&Wres[k * OC + c]), acc);
    }
    acc += m_tp + m_int;
    float h = fmaxf(acc, 0.f);
    int o = node * OC + c;
    g_h[o] = h;

    // block-2 transforms, both matrices share the h broadcasts
    float atp = 0.f, ain = 0.f;
#pragma unroll
    for (int p = 0; p < 16; p++) {
        float ha = __shfl_sync(FULL, h, 2 * p);
        float hb = __shfl_sync(FULL, h, 2 * p + 1);
        float2 wt = sWtp[p * 32 + c];
        float2 wi = sWint[p * 32 + c];
        atp = fmaf(ha, wt.x, fmaf(hb, wt.y, atp));
        ain = fmaf(ha, wi.x, fmaf(hb, wi.y, ain));
    }
    g_y_tp2[o]  = __float2half(atp);
    g_y_int2[o] = __float2half(ain);
}

// ------------------------------------------------------------------
// combine block 2 (identity residual) + decoder MLP + sigmoid.
__global__ void k_combine2(const float* __restrict__ Ws2,
                           const float* __restrict__ b2,
                           const float* __restrict__ Wd1,
                           const float* __restrict__ bd1,
                           const float* __restrict__ Wd2,
                           const float* __restrict__ bd2,
                           float* __restrict__ out,
                           int n_node) {
    __shared__ float2 sWs[16 * 32];
    __shared__ float2 sWd1[16 * 32];
    for (int i = threadIdx.x; i < 16 * 32; i += blockDim.x) {
        int p = i >> 5, cc = i & 31;
        sWs[i]  = make_float2(Ws2[(2 * p) * OC + cc], Ws2[(2 * p + 1) * OC + cc]);
        sWd1[i] = make_float2(Wd1[(2 * p) * OC + cc], Wd1[(2 * p + 1) * OC + cc]);
    }
    __syncthreads();

    int t = blockIdx.x * blockDim.x + threadIdx.x;
    int node = t >> 5;
    int c = t & 31;
    if (node >= n_node) return;

    float2 a_tp  = gather_pair(g_csr_tp,  g_off_tp[node],  g_off_tp[node + 1],
                               (const __half2*)g_y_tp2,  c);
    float2 a_int = gather_pair(g_csr_int, g_off_int[node], g_off_int[node + 1],
                               (const __half2*)g_y_int2, c);
    float m_tp  = pair_to_lane(a_tp, c);
    float m_int = pair_to_lane(a_int, c) * g_inv[node];

    int o = node * OC + c;
    float h = g_h[o];
    float acc = __ldg(&b2[c]) + h;      // identity residual
#pragma unroll
    for (int p = 0; p < 16; p++) {
        float ha = __shfl_sync(FULL, h, 2 * p);
        float hb = __shfl_sync(FULL, h, 2 * p + 1);
        float2 w = sWs[p * 32 + c];
        acc = fmaf(ha, w.x, fmaf(hb, w.y, acc));
    }
    acc += m_tp + m_int;
    float h2 = fmaxf(acc, 0.f);

    float d = __ldg(&bd1[c]);
#pragma unroll
    for (int p = 0; p < 16; p++) {
        float ha = __shfl_sync(FULL, h2, 2 * p);
        float hb = __shfl_sync(FULL, h2, 2 * p + 1);
        float2 w = sWd1[p * 32 + c];
        d = fmaf(ha, w.x, fmaf(hb, w.y, d));
    }
    d = fmaxf(d, 0.f) * __ldg(&Wd2[c]);

#pragma unroll
    for (int off = 16; off > 0; off >>= 1)
        d += __shfl_xor_sync(FULL, d, off);

    if (c == 0)
        out[node] = 1.f / (1.f + __expf(-(d + __ldg(&bd2[0]))));
}

// ------------------------------------------------------------------
extern "C" void kernel_launch(void* const* d_in, const int* in_sizes, int n_in,
                              void* d_out, int out_size) {
    const float* x        = (const float*)d_in[0];
    const int*   edge_tp  = (const int*)d_in[1];
    const int*   edge_int = (const int*)d_in[2];
    const float* W_self1  = (const float*)d_in[3];
    const float* b1       = (const float*)d_in[4];
    const float* W_tp1    = (const float*)d_in[5];
    const float* W_int1   = (const float*)d_in[6];
    const float* W_res1   = (const float*)d_in[7];
    const float* W_self2  = (const float*)d_in[8];
    const float* b2       = (const float*)d_in[9];
    const float* W_tp2    = (const float*)d_in[10];
    const float* W_int2   = (const float*)d_in[11];
    const float* Wd1      = (const float*)d_in[12];
    const float* bd1      = (const float*)d_in[13];
    const float* Wd2      = (const float*)d_in[14];
    const float* bd2      = (const float*)d_in[15];
    float* out = (float*)d_out;

    const int N = in_sizes[0] / 6;        // 100000
    const int E = in_sizes[1] / 2;        // 1600000

    const int* tp_src  = edge_tp;
    const int* tp_dst  = edge_tp + E;
    const int* int_src = edge_int;
    const int* int_dst = edge_int + E;

    const int TB = 256;
    const int gNode = (N * OC + TB - 1) / TB;
    long long work  = (long long)2 * E;
    if ((long long)N * OC > work) work = (long long)N * OC;
    const int gBig  = (int)((work + TB - 1) / TB);
    const int gE2   = (2 * E + TB - 1) / TB;
    const int nb    = (N + TILE - 1) / TILE;

    // 5-launch pipeline (combine1 = launch index 3 -> gets profiled)
    k_count_transform<<<gBig, TB>>>(tp_dst, int_dst, x, W_tp1, W_int1, E, N);
    k_scan<<<2 * nb, TB>>>(N, nb);
    k_fill<<<gE2, TB>>>(tp_src, tp_dst, int_src, int_dst, E);
    k_combine1<<<gNode, TB>>>(x, W_self1, b1, W_res1, W_tp2, W_int2, N);
    k_combine2<<<gNode, TB>>>(W_self2, b2, Wd1, bd1, Wd2, bd2, out, N);
}